// round 4
// baseline (speedup 1.0000x reference)
#include <cuda_runtime.h>
#include <cuda_bf16.h>
#include <mma.h>
#include <cstdint>

using namespace nvcuda;

#define NAG  8192
#define OBSD 64
#define HID  128
#define ACTD 16

// Scratch (device globals: no allocations allowed)
__device__ float          g_h  [NAG * HID];   // fp32 encoder output
__device__ __nv_bfloat16  g_hbT[HID * NAG];   // bf16 h TRANSPOSED: [col][agent]
__device__ float          g_msg[NAG * HID];   // neighbor-mean messages

// ---------------------------------------------------------------------------
// K1: h = tanh(obs @ W1 + b1) -> g_h (fp32) and g_hbT (bf16, transposed).
// 256 CTAs x 256 threads, 32 agents per CTA.
// ---------------------------------------------------------------------------
__global__ void __launch_bounds__(256) k1_encoder(const float* __restrict__ obs,
                                                  const float* __restrict__ W1,
                                                  const float* __restrict__ b1) {
    __shared__ __align__(16) float sW1[OBSD * HID];     // 32 KB
    __shared__ float sObs[32][OBSD];                    // 8 KB
    __shared__ unsigned short sT[32][130];              // bf16 bits, padded
    const int t  = threadIdx.x;
    const int a0 = blockIdx.x * 32;

    #pragma unroll 8
    for (int i = 0; i < (OBSD * HID) / 256; ++i)
        sW1[i * 256 + t] = W1[i * 256 + t];
    #pragma unroll
    for (int i = 0; i < 8; ++i) {
        int idx = i * 256 + t;
        sObs[idx >> 6][idx & 63] = obs[(size_t)(a0 + (idx >> 6)) * OBSD + (idx & 63)];
    }
    __syncthreads();

    const int w = t >> 5, l = t & 31;
    float4 bb = *reinterpret_cast<const float4*>(&b1[l * 4]);
    #pragma unroll
    for (int it = 0; it < 4; ++it) {
        const int a = it * 8 + w;
        float acc0 = 0.f, acc1 = 0.f, acc2 = 0.f, acc3 = 0.f;
        #pragma unroll 8
        for (int k = 0; k < OBSD; ++k) {
            float o = sObs[a][k];
            float4 wv = *reinterpret_cast<const float4*>(&sW1[k * HID + l * 4]);
            acc0 = fmaf(o, wv.x, acc0);
            acc1 = fmaf(o, wv.y, acc1);
            acc2 = fmaf(o, wv.z, acc2);
            acc3 = fmaf(o, wv.w, acc3);
        }
        float h0 = tanhf(acc0 + bb.x), h1 = tanhf(acc1 + bb.y);
        float h2 = tanhf(acc2 + bb.z), h3 = tanhf(acc3 + bb.w);
        float4 hv; hv.x = h0; hv.y = h1; hv.z = h2; hv.w = h3;
        *reinterpret_cast<float4*>(&g_h[(size_t)(a0 + a) * HID + l * 4]) = hv;
        __nv_bfloat16 v0 = __float2bfloat16(h0), v1 = __float2bfloat16(h1);
        __nv_bfloat16 v2 = __float2bfloat16(h2), v3 = __float2bfloat16(h3);
        sT[a][l * 4 + 0] = *reinterpret_cast<unsigned short*>(&v0);
        sT[a][l * 4 + 1] = *reinterpret_cast<unsigned short*>(&v1);
        sT[a][l * 4 + 2] = *reinterpret_cast<unsigned short*>(&v2);
        sT[a][l * 4 + 3] = *reinterpret_cast<unsigned short*>(&v3);
    }
    __syncthreads();

    if (t < HID) {      // column t: pack 32 agents -> 64B contiguous in g_hbT
        unsigned r[16];
        #pragma unroll
        for (int j = 0; j < 16; ++j)
            r[j] = (unsigned)sT[2 * j][t] | ((unsigned)sT[2 * j + 1][t] << 16);
        uint4* dst = reinterpret_cast<uint4*>(g_hbT + (size_t)t * NAG + a0);
        dst[0] = make_uint4(r[0],  r[1],  r[2],  r[3]);
        dst[1] = make_uint4(r[4],  r[5],  r[6],  r[7]);
        dst[2] = make_uint4(r[8],  r[9],  r[10], r[11]);
        dst[3] = make_uint4(r[12], r[13], r[14], r[15]);
    }
}

// ---------------------------------------------------------------------------
// K2: msg = (adj @ h) / max(deg,1) via warp-specialized WMMA.
// 128 CTAs; tile M=64 rows x N=128 cols; K=8192 in 128 chunks of 64.
// Warps 0-3 produce (LDG + int32->bf16 pack + STS), warps 4-7 consume (MMA).
// Double-buffered smem; ONE __syncthreads per chunk.
// A buf: bf16 [64][72] (9216 B). B buf: bf16 [128][136] col-major-n (34816 B).
// ---------------------------------------------------------------------------
__device__ __forceinline__ unsigned pack2(int a, int b) {
    return (a ? 0x3F80u : 0u) | (b ? 0x3F800000u : 0u);   // two bf16 {0,1}
}
__device__ __forceinline__ int nz4(int4 v) {
    return (v.x != 0) + (v.y != 0) + (v.z != 0) + (v.w != 0);
}

#define K2_BUF   (9216 + 34816)           // 44,032 B per buffer
#define K2_SMEM  (2 * K2_BUF)             // 88,064 B

__global__ void __launch_bounds__(256, 1) k2_msg(const int* __restrict__ adj) {
    extern __shared__ __align__(16) char sm2[];
    __shared__ int sDeg[64];

    const int t   = threadIdx.x;
    const int wid = t >> 5;
    const int m0  = blockIdx.x * 64;
    if (t < 64) sDeg[t] = 0;

    // producer mapping: pt in [0,128): row r = pt>>1, half = pt&1 (k-offset half*32)
    const int r    = (t & 127) >> 1;
    const int half = t & 1;
    const int4*  gA  = reinterpret_cast<const int4*>(adj + (size_t)(m0 + r) * NAG) + half * 8;
    const uint4* gB1 = reinterpret_cast<const uint4*>(g_hbT + (size_t)r        * NAG) + half * 4;
    const uint4* gB2 = reinterpret_cast<const uint4*>(g_hbT + (size_t)(r + 64) * NAG) + half * 4;

    // consumer mapping: warps 4-7 -> 2x2 grid of 32M x 64N tiles
    const int cw = wid - 4;
    const int wm = cw & 1;       // M block (32 rows)
    const int wn = cw >> 1;      // N block (64 cols)

    int4  ra[8];
    uint4 rb[8];
    int   cnt = 0;
    if (wid < 4) {
        #pragma unroll
        for (int i = 0; i < 8; ++i) ra[i] = gA[i];
        #pragma unroll
        for (int i = 0; i < 4; ++i) { rb[i] = gB1[i]; rb[4 + i] = gB2[i]; }
    }

    wmma::fragment<wmma::accumulator, 16, 16, 16, float> acc[2][4];
    if (wid >= 4) {
        #pragma unroll
        for (int i = 0; i < 2; ++i)
            #pragma unroll
            for (int j = 0; j < 4; ++j)
                wmma::fill_fragment(acc[i][j], 0.0f);
    }

    const int NCH = NAG / 64;     // 128
    for (int c = 0; c < NCH; ++c) {
        char* bufA = sm2 + (c & 1) * K2_BUF;
        char* bufB = bufA + 9216;

        if (wid < 4) {
            // ---- stage chunk c ----
            #pragma unroll
            for (int q = 0; q < 4; ++q) {
                int4 v0 = ra[2 * q], v1 = ra[2 * q + 1];
                uint4 wv;
                wv.x = pack2(v0.x, v0.y); wv.y = pack2(v0.z, v0.w);
                wv.z = pack2(v1.x, v1.y); wv.w = pack2(v1.z, v1.w);
                cnt += nz4(v0) + nz4(v1);
                *reinterpret_cast<uint4*>(bufA + r * 144 + half * 64 + q * 16) = wv;
            }
            #pragma unroll
            for (int q = 0; q < 4; ++q)
                *reinterpret_cast<uint4*>(bufB + r * 272 + half * 64 + q * 16) = rb[q];
            #pragma unroll
            for (int q = 0; q < 4; ++q)
                *reinterpret_cast<uint4*>(bufB + (r + 64) * 272 + half * 64 + q * 16) = rb[4 + q];
        }
        __syncthreads();

        if (wid < 4) {
            // ---- prefetch chunk c+1 (LDG latency hidden under consumers' MMA) ----
            if (c + 1 < NCH) {
                #pragma unroll
                for (int i = 0; i < 8; ++i) ra[i] = gA[(c + 1) * 16 + i];
                #pragma unroll
                for (int i = 0; i < 4; ++i) {
                    rb[i]     = gB1[(c + 1) * 8 + i];
                    rb[4 + i] = gB2[(c + 1) * 8 + i];
                }
            }
        } else {
            // ---- MMA chunk c ----
            const __nv_bfloat16* sA = reinterpret_cast<const __nv_bfloat16*>(bufA);
            const __nv_bfloat16* sB = reinterpret_cast<const __nv_bfloat16*>(bufB);
            #pragma unroll
            for (int ks = 0; ks < 4; ++ks) {
                wmma::fragment<wmma::matrix_a, 16, 16, 16, __nv_bfloat16, wmma::row_major> af[2];
                wmma::fragment<wmma::matrix_b, 16, 16, 16, __nv_bfloat16, wmma::col_major> bf[4];
                #pragma unroll
                for (int i = 0; i < 2; ++i)
                    wmma::load_matrix_sync(af[i], &sA[(wm * 32 + i * 16) * 72 + ks * 16], 72);
                #pragma unroll
                for (int j = 0; j < 4; ++j)
                    wmma::load_matrix_sync(bf[j], &sB[(wn * 64 + j * 16) * 136 + ks * 16], 136);
                #pragma unroll
                for (int i = 0; i < 2; ++i)
                    #pragma unroll
                    for (int j = 0; j < 4; ++j)
                        wmma::mma_sync(acc[i][j], af[i], bf[j], acc[i][j]);
            }
        }
    }

    if (wid < 4) atomicAdd(&sDeg[r], cnt);
    __syncthreads();

    // epilogue: acc -> smem (fp32 [64][132]) -> scaled write to g_msg
    float* sAcc = reinterpret_cast<float*>(sm2);
    if (wid >= 4) {
        #pragma unroll
        for (int i = 0; i < 2; ++i)
            #pragma unroll
            for (int j = 0; j < 4; ++j)
                wmma::store_matrix_sync(&sAcc[(wm * 32 + i * 16) * 132 + wn * 64 + j * 16],
                                        acc[i][j], 132, wmma::mem_row_major);
    }
    __syncthreads();

    #pragma unroll
    for (int i = 0; i < 32; ++i) {
        int idx = i * 256 + t;                 // 8192 outputs
        int row = idx >> 7, col = idx & 127;
        float s = 1.0f / (float)max(sDeg[row], 1);
        g_msg[(size_t)(m0 + row) * HID + col] = sAcc[row * 132 + col] * s;
    }
}

// ---------------------------------------------------------------------------
// K3: hid = tanh([h,msg] @ W2 + b2); logits = hid @ W3 + b3.
// 128 CTAs x 64 agents; W2 fully in smem (128KB). Thread computes 4x8 hid tile.
// ---------------------------------------------------------------------------
#define K3_SMEM (4 * (32768 + 16448 + 2048 + 128 + 16))   // 205,632 B

__global__ void __launch_bounds__(256, 1) k3_actor(float* __restrict__ out,
        const float* __restrict__ W2, const float* __restrict__ b2,
        const float* __restrict__ W3, const float* __restrict__ b3) {
    extern __shared__ __align__(16) float sm[];
    float* sW2 = sm;                   // [256][128]
    float* sC  = sm + 32768;           // [64][257] combined; reused as hid [64][129]
    float* sW3 = sC + 16448;           // [128][16]
    float* sb2 = sW3 + 2048;           // [128]
    float* sb3 = sb2 + 128;            // [16]

    const int t  = threadIdx.x;
    const int a0 = blockIdx.x * 64;

    #pragma unroll 4
    for (int i = 0; i < 128; ++i) sW2[i * 256 + t] = W2[i * 256 + t];
    #pragma unroll
    for (int i = 0; i < 8; ++i)   sW3[i * 256 + t] = W3[i * 256 + t];
    if (t < 128) sb2[t] = b2[t];
    if (t < 16)  sb3[t] = b3[t];
    #pragma unroll 4
    for (int i = 0; i < 32; ++i) {
        int idx = i * 256 + t;             // 8192 (agent,col) pairs
        int a = idx >> 7, k = idx & 127;
        sC[a * 257 + k]       = g_h  [(size_t)(a0 + a) * HID + k];
        sC[a * 257 + 128 + k] = g_msg[(size_t)(a0 + a) * HID + k];
    }
    __syncthreads();

    const int ar = t >> 4;    // agents ar*4 .. ar*4+3
    const int cc = t & 15;    // cols cc*8 .. cc*8+7
    float acc[4][8];
    #pragma unroll
    for (int j = 0; j < 4; ++j)
        #pragma unroll
        for (int i = 0; i < 8; ++i) acc[j][i] = 0.f;

    #pragma unroll 2
    for (int k = 0; k < 2 * HID; ++k) {
        float4 w0 = *reinterpret_cast<const float4*>(&sW2[k * 128 + cc * 8]);
        float4 w1 = *reinterpret_cast<const float4*>(&sW2[k * 128 + cc * 8 + 4]);
        #pragma unroll
        for (int j = 0; j < 4; ++j) {
            float cv = sC[(ar * 4 + j) * 257 + k];
            acc[j][0] = fmaf(cv, w0.x, acc[j][0]);
            acc[j][1] = fmaf(cv, w0.y, acc[j][1]);
            acc[j][2] = fmaf(cv, w0.z, acc[j][2]);
            acc[j][3] = fmaf(cv, w0.w, acc[j][3]);
            acc[j][4] = fmaf(cv, w1.x, acc[j][4]);
            acc[j][5] = fmaf(cv, w1.y, acc[j][5]);
            acc[j][6] = fmaf(cv, w1.z, acc[j][6]);
            acc[j][7] = fmaf(cv, w1.w, acc[j][7]);
        }
    }
    __syncthreads();                      // all comb reads done; reuse sC as hid
    float* sH = sC;                       // [64][129]
    #pragma unroll
    for (int j = 0; j < 4; ++j) {
        int a = ar * 4 + j;
        #pragma unroll
        for (int i = 0; i < 8; ++i) {
            int ccol = cc * 8 + i;
            sH[a * 129 + ccol] = tanhf(acc[j][i] + sb2[ccol]);
        }
    }
    __syncthreads();

    const int a  = t >> 2;   // 0..63
    const int cq = t & 3;    // col quad
    float4 lg; lg.x = 0.f; lg.y = 0.f; lg.z = 0.f; lg.w = 0.f;
    #pragma unroll 8
    for (int k = 0; k < HID; ++k) {
        float hv  = sH[a * 129 + k];
        float4 w3 = *reinterpret_cast<const float4*>(&sW3[k * 16 + cq * 4]);
        lg.x = fmaf(hv, w3.x, lg.x);
        lg.y = fmaf(hv, w3.y, lg.y);
        lg.z = fmaf(hv, w3.z, lg.z);
        lg.w = fmaf(hv, w3.w, lg.w);
    }
    lg.x += sb3[cq * 4 + 0];
    lg.y += sb3[cq * 4 + 1];
    lg.z += sb3[cq * 4 + 2];
    lg.w += sb3[cq * 4 + 3];
    *reinterpret_cast<float4*>(&out[(size_t)(a0 + a) * ACTD + cq * 4]) = lg;
}

// ---------------------------------------------------------------------------
extern "C" void kernel_launch(void* const* d_in, const int* in_sizes, int n_in,
                              void* d_out, int out_size) {
    const float* obs = (const float*)d_in[0];
    const int*   adj = (const int*)  d_in[1];
    const float* W1  = (const float*)d_in[2];
    const float* b1  = (const float*)d_in[3];
    const float* W2  = (const float*)d_in[4];
    const float* b2  = (const float*)d_in[5];
    const float* W3  = (const float*)d_in[6];
    const float* b3  = (const float*)d_in[7];
    float* out = (float*)d_out;

    cudaFuncSetAttribute(k2_msg,   cudaFuncAttributeMaxDynamicSharedMemorySize, K2_SMEM);
    cudaFuncSetAttribute(k3_actor, cudaFuncAttributeMaxDynamicSharedMemorySize, K3_SMEM);

    k1_encoder<<<NAG / 32, 256>>>(obs, W1, b1);
    k2_msg    <<<NAG / 64, 256, K2_SMEM>>>(adj);
    k3_actor  <<<NAG / 64, 256, K3_SMEM>>>(out, W2, b2, W3, b3);
}

// round 5
// speedup vs baseline: 1.1362x; 1.1362x over previous
#include <cuda_runtime.h>
#include <cuda_bf16.h>
#include <cuda_pipeline.h>
#include <mma.h>
#include <cstdint>

using namespace nvcuda;

#define NAG  8192
#define OBSD 64
#define HID  128
#define ACTD 16

// Scratch (device globals: no allocations allowed)
__device__ float          g_h  [NAG * HID];   // fp32 encoder output
__device__ __nv_bfloat16  g_hb [NAG * HID];   // bf16 copy (row-major, agent x col)
__device__ float          g_msg[NAG * HID];   // neighbor-mean messages

// ---------------------------------------------------------------------------
// K1: h = tanh(obs @ W1 + b1), also emit bf16 copy. (round-1 version: fastest)
// 1024 CTAs x 256 threads; one warp per agent, lane l owns cols 4l..4l+3.
// ---------------------------------------------------------------------------
__global__ void __launch_bounds__(256) k1_encoder(const float* __restrict__ obs,
                                                  const float* __restrict__ W1,
                                                  const float* __restrict__ b1) {
    __shared__ __align__(16) float sW1[OBSD * HID];   // 32 KB
    __shared__ float sObs[8][OBSD];                   // 2 KB
    const int t  = threadIdx.x;
    const int a0 = blockIdx.x * 8;

    #pragma unroll
    for (int i = 0; i < (OBSD * HID) / 256; ++i)
        sW1[i * 256 + t] = W1[i * 256 + t];
    #pragma unroll
    for (int i = 0; i < 2; ++i) {
        int idx = i * 256 + t;               // 512 obs floats
        sObs[idx >> 6][idx & 63] = obs[(size_t)(a0 + (idx >> 6)) * OBSD + (idx & 63)];
    }
    __syncthreads();

    const int w = t >> 5, l = t & 31;
    const int agent = a0 + w;
    float acc0 = 0.f, acc1 = 0.f, acc2 = 0.f, acc3 = 0.f;
    #pragma unroll 8
    for (int k = 0; k < OBSD; ++k) {
        float o = sObs[w][k];
        float4 wv = *reinterpret_cast<const float4*>(&sW1[k * HID + l * 4]);
        acc0 = fmaf(o, wv.x, acc0);
        acc1 = fmaf(o, wv.y, acc1);
        acc2 = fmaf(o, wv.z, acc2);
        acc3 = fmaf(o, wv.w, acc3);
    }
    float4 bb = *reinterpret_cast<const float4*>(&b1[l * 4]);
    float h0 = tanhf(acc0 + bb.x);
    float h1 = tanhf(acc1 + bb.y);
    float h2 = tanhf(acc2 + bb.z);
    float h3 = tanhf(acc3 + bb.w);

    const size_t off = (size_t)agent * HID + l * 4;
    float4 hv; hv.x = h0; hv.y = h1; hv.z = h2; hv.w = h3;
    *reinterpret_cast<float4*>(&g_h[off]) = hv;
    __nv_bfloat162 p0 = __floats2bfloat162_rn(h0, h1);
    __nv_bfloat162 p1 = __floats2bfloat162_rn(h2, h3);
    *reinterpret_cast<__nv_bfloat162*>(&g_hb[off])     = p0;
    *reinterpret_cast<__nv_bfloat162*>(&g_hb[off + 2]) = p1;
}

// ---------------------------------------------------------------------------
// K2: msg = (adj @ h) / max(deg,1). cp.async 4-deep ring + WMMA.
// 128 CTAs; tile M=64 x N=128; K=8192 in 128 chunks of 64.
// Stage: A raw int32 [64][272B] + B bf16 [64][272B]. Converted A: [64][144B] x2.
// Per chunk: wait -> convert(own data) -> ONE barrier -> issue c+3 -> MMA.
// 8 warps, 32x64 warp tiles, 2-way ks split; partials merged in epilogue.
// ---------------------------------------------------------------------------
__device__ __forceinline__ unsigned pack2i(int a, int b) {
    return (a ? 0x3F80u : 0u) | (b ? 0x3F800000u : 0u);   // two bf16 {0,1}
}
__device__ __forceinline__ int nz4(int4 v) {
    return (v.x != 0) + (v.y != 0) + (v.z != 0) + (v.w != 0);
}

#define K2_STAGE   34816            // 17408 (A raw) + 17408 (B)
#define K2_RING    (4 * K2_STAGE)   // 139264
#define K2_ABF     9216             // 64 x 144 B converted A
#define K2_SMEM    (K2_RING + 2 * K2_ABF)   // 157696
#define NCH        (NAG / 64)       // 128

__global__ void __launch_bounds__(256, 1) k2_msg(const int* __restrict__ adj) {
    extern __shared__ __align__(16) char sm2[];
    __shared__ int sDeg[64];

    const int t   = threadIdx.x;
    const int wid = t >> 5;
    const int m0  = blockIdx.x * 64;
    if (t < 64) sDeg[t] = 0;

    // per-thread tile coords for issue+convert: row irow, 16-col group ig
    const int irow = t >> 2;
    const int ig   = t & 3;

    const char* gA = reinterpret_cast<const char*>(adj) +
                     (size_t)(m0 + irow) * (NAG * 4) + ig * 64;   // + c*256 per chunk
    const char* gB = reinterpret_cast<const char*>(g_hb) +
                     (size_t)irow * (HID * 2) + ig * 64;          // + c*64*256 per chunk

    // warp MMA mapping: wm = M half (32 rows), wn = N half (64 cols), kh = ks half
    const int wm = wid & 1;
    const int wn = (wid >> 1) & 1;
    const int kh = wid >> 2;

    wmma::fragment<wmma::accumulator, 16, 16, 16, float> acc[2][4];
    #pragma unroll
    for (int i = 0; i < 2; ++i)
        #pragma unroll
        for (int j = 0; j < 4; ++j)
            wmma::fill_fragment(acc[i][j], 0.0f);

    // ---- issue helper: stage chunk c into ring slot c&3 ----
    auto issue_stage = [&](int c) {
        char* sA = sm2 + (c & 3) * K2_STAGE;
        char* sB = sA + 17408;
        const char* ga = gA + (size_t)c * 256;
        const char* gb = gB + (size_t)c * 64 * 256;
        #pragma unroll
        for (int q = 0; q < 4; ++q)
            __pipeline_memcpy_async(sA + irow * 272 + ig * 64 + q * 16, ga + q * 16, 16);
        #pragma unroll
        for (int q = 0; q < 4; ++q)
            __pipeline_memcpy_async(sB + irow * 272 + ig * 64 + q * 16, gb + q * 16, 16);
    };

    issue_stage(0); __pipeline_commit();
    issue_stage(1); __pipeline_commit();
    issue_stage(2); __pipeline_commit();

    int cnt = 0;
    for (int c = 0; c < NCH; ++c) {
        char* sAraw = sm2 + (c & 3) * K2_STAGE;
        char* sBc   = sAraw + 17408;
        char* sAbf  = sm2 + K2_RING + (c & 1) * K2_ABF;

        __pipeline_wait_prior(2);      // stage c arrived (this thread's issues)

        // convert own A words: 16 int32 -> 16 bf16 (32 B)
        {
            const int4* src = reinterpret_cast<const int4*>(sAraw + irow * 272 + ig * 64);
            int4 v0 = src[0], v1 = src[1], v2 = src[2], v3 = src[3];
            cnt += nz4(v0) + nz4(v1) + nz4(v2) + nz4(v3);
            uint4 w0, w1;
            w0.x = pack2i(v0.x, v0.y); w0.y = pack2i(v0.z, v0.w);
            w0.z = pack2i(v1.x, v1.y); w0.w = pack2i(v1.z, v1.w);
            w1.x = pack2i(v2.x, v2.y); w1.y = pack2i(v2.z, v2.w);
            w1.z = pack2i(v3.x, v3.y); w1.w = pack2i(v3.z, v3.w);
            uint4* dst = reinterpret_cast<uint4*>(sAbf + irow * 144 + ig * 32);
            dst[0] = w0; dst[1] = w1;
        }
        __syncthreads();               // A-bf16 + B visible to all

        // keep the pipeline fed (empty commits keep group accounting uniform)
        if (c + 3 < NCH) issue_stage(c + 3);
        __pipeline_commit();

        // MMA chunk c: warp tile 32x64, ks in {2*kh, 2*kh+1}
        const __nv_bfloat16* A = reinterpret_cast<const __nv_bfloat16*>(sAbf);
        const __nv_bfloat16* B = reinterpret_cast<const __nv_bfloat16*>(sBc);
        #pragma unroll
        for (int s = 0; s < 2; ++s) {
            const int ks = kh * 2 + s;
            wmma::fragment<wmma::matrix_a, 16, 16, 16, __nv_bfloat16, wmma::row_major> af[2];
            wmma::fragment<wmma::matrix_b, 16, 16, 16, __nv_bfloat16, wmma::row_major> bf[4];
            #pragma unroll
            for (int i = 0; i < 2; ++i)
                wmma::load_matrix_sync(af[i], &A[(wm * 32 + i * 16) * 72 + ks * 16], 72);
            #pragma unroll
            for (int j = 0; j < 4; ++j)
                wmma::load_matrix_sync(bf[j], &B[(ks * 16) * 136 + wn * 64 + j * 16], 136);
            #pragma unroll
            for (int i = 0; i < 2; ++i)
                #pragma unroll
                for (int j = 0; j < 4; ++j)
                    wmma::mma_sync(acc[i][j], af[i], bf[j], acc[i][j]);
        }
    }

    atomicAdd(&sDeg[irow], cnt);

    // epilogue: two partial [64][132] fp32 tiles (one per ks-half), then merge
    float* sAcc0 = reinterpret_cast<float*>(sm2);
    float* sAcc1 = reinterpret_cast<float*>(sm2 + 33792);
    float* dstAcc = kh ? sAcc1 : sAcc0;
    #pragma unroll
    for (int i = 0; i < 2; ++i)
        #pragma unroll
        for (int j = 0; j < 4; ++j)
            wmma::store_matrix_sync(&dstAcc[(wm * 32 + i * 16) * 132 + wn * 64 + j * 16],
                                    acc[i][j], 132, wmma::mem_row_major);
    __syncthreads();

    #pragma unroll
    for (int i = 0; i < 32; ++i) {
        int idx = i * 256 + t;                 // 8192 outputs
        int row = idx >> 7, col = idx & 127;
        float s = 1.0f / (float)max(sDeg[row], 1);
        g_msg[(size_t)(m0 + row) * HID + col] =
            (sAcc0[row * 132 + col] + sAcc1[row * 132 + col]) * s;
    }
}

// ---------------------------------------------------------------------------
// K3: hid = tanh([h,msg] @ W2 + b2); logits = hid @ W3 + b3.
// 128 CTAs x 64 agents; W2 fully in smem (128KB). Thread computes 4x8 hid tile.
// ---------------------------------------------------------------------------
#define K3_SMEM (4 * (32768 + 16448 + 2048 + 128 + 16))   // 205,632 B

__global__ void __launch_bounds__(256, 1) k3_actor(float* __restrict__ out,
        const float* __restrict__ W2, const float* __restrict__ b2,
        const float* __restrict__ W3, const float* __restrict__ b3) {
    extern __shared__ __align__(16) float sm[];
    float* sW2 = sm;                   // [256][128]
    float* sC  = sm + 32768;           // [64][257] combined; reused as hid [64][129]
    float* sW3 = sC + 16448;           // [128][16]
    float* sb2 = sW3 + 2048;           // [128]
    float* sb3 = sb2 + 128;            // [16]

    const int t  = threadIdx.x;
    const int a0 = blockIdx.x * 64;

    #pragma unroll 4
    for (int i = 0; i < 128; ++i) sW2[i * 256 + t] = W2[i * 256 + t];
    #pragma unroll
    for (int i = 0; i < 8; ++i)   sW3[i * 256 + t] = W3[i * 256 + t];
    if (t < 128) sb2[t] = b2[t];
    if (t < 16)  sb3[t] = b3[t];
    #pragma unroll 4
    for (int i = 0; i < 32; ++i) {
        int idx = i * 256 + t;             // 8192 (agent,col) pairs
        int a = idx >> 7, k = idx & 127;
        sC[a * 257 + k]       = g_h  [(size_t)(a0 + a) * HID + k];
        sC[a * 257 + 128 + k] = g_msg[(size_t)(a0 + a) * HID + k];
    }
    __syncthreads();

    const int ar = t >> 4;    // agents ar*4 .. ar*4+3
    const int cc = t & 15;    // cols cc*8 .. cc*8+7
    float acc[4][8];
    #pragma unroll
    for (int j = 0; j < 4; ++j)
        #pragma unroll
        for (int i = 0; i < 8; ++i) acc[j][i] = 0.f;

    #pragma unroll 2
    for (int k = 0; k < 2 * HID; ++k) {
        float4 w0 = *reinterpret_cast<const float4*>(&sW2[k * 128 + cc * 8]);
        float4 w1 = *reinterpret_cast<const float4*>(&sW2[k * 128 + cc * 8 + 4]);
        #pragma unroll
        for (int j = 0; j < 4; ++j) {
            float cv = sC[(ar * 4 + j) * 257 + k];
            acc[j][0] = fmaf(cv, w0.x, acc[j][0]);
            acc[j][1] = fmaf(cv, w0.y, acc[j][1]);
            acc[j][2] = fmaf(cv, w0.z, acc[j][2]);
            acc[j][3] = fmaf(cv, w0.w, acc[j][3]);
            acc[j][4] = fmaf(cv, w1.x, acc[j][4]);
            acc[j][5] = fmaf(cv, w1.y, acc[j][5]);
            acc[j][6] = fmaf(cv, w1.z, acc[j][6]);
            acc[j][7] = fmaf(cv, w1.w, acc[j][7]);
        }
    }
    __syncthreads();                      // all comb reads done; reuse sC as hid
    float* sH = sC;                       // [64][129]
    #pragma unroll
    for (int j = 0; j < 4; ++j) {
        int a = ar * 4 + j;
        #pragma unroll
        for (int i = 0; i < 8; ++i) {
            int ccol = cc * 8 + i;
            sH[a * 129 + ccol] = tanhf(acc[j][i] + sb2[ccol]);
        }
    }
    __syncthreads();

    const int a  = t >> 2;   // 0..63
    const int cq = t & 3;    // col quad
    float4 lg; lg.x = 0.f; lg.y = 0.f; lg.z = 0.f; lg.w = 0.f;
    #pragma unroll 8
    for (int k = 0; k < HID; ++k) {
        float hv  = sH[a * 129 + k];
        float4 w3 = *reinterpret_cast<const float4*>(&sW3[k * 16 + cq * 4]);
        lg.x = fmaf(hv, w3.x, lg.x);
        lg.y = fmaf(hv, w3.y, lg.y);
        lg.z = fmaf(hv, w3.z, lg.z);
        lg.w = fmaf(hv, w3.w, lg.w);
    }
    lg.x += sb3[cq * 4 + 0];
    lg.y += sb3[cq * 4 + 1];
    lg.z += sb3[cq * 4 + 2];
    lg.w += sb3[cq * 4 + 3];
    *reinterpret_cast<float4*>(&out[(size_t)(a0 + a) * ACTD + cq * 4]) = lg;
}

// ---------------------------------------------------------------------------
extern "C" void kernel_launch(void* const* d_in, const int* in_sizes, int n_in,
                              void* d_out, int out_size) {
    const float* obs = (const float*)d_in[0];
    const int*   adj = (const int*)  d_in[1];
    const float* W1  = (const float*)d_in[2];
    const float* b1  = (const float*)d_in[3];
    const float* W2  = (const float*)d_in[4];
    const float* b2  = (const float*)d_in[5];
    const float* W3  = (const float*)d_in[6];
    const float* b3  = (const float*)d_in[7];
    float* out = (float*)d_out;

    cudaFuncSetAttribute(k2_msg,   cudaFuncAttributeMaxDynamicSharedMemorySize, K2_SMEM);
    cudaFuncSetAttribute(k3_actor, cudaFuncAttributeMaxDynamicSharedMemorySize, K3_SMEM);

    k1_encoder<<<NAG / 8, 256>>>(obs, W1, b1);
    k2_msg    <<<NAG / 64, 256, K2_SMEM>>>(adj);
    k3_actor  <<<NAG / 64, 256, K3_SMEM>>>(out, W2, b2, W3, b3);
}